// round 9
// baseline (speedup 1.0000x reference)
#include <cuda_runtime.h>
#include <math.h>

#define Nn 8192
#define Fin 64
#define CAP 320     // max nonzeros/row: Binomial(8192,0.02): mean 164, sd 12.7 -> +12 sigma

// Scratch (device globals, no allocation)
__device__ float g_hatt[Nn * Fin];                       // h @ W_att
__device__ float g_e[Nn];                                // leaky_relu(|h+ - h-| @ a)
__device__ unsigned long long g_list[(size_t)Nn * CAP];  // packed (val<<32 | j) per edge nonzero
__device__ int g_cnt[Nn];                                // edge nonzeros per row

// ---------------------------------------------------------------------------
// Kernel 1: h_att = h @ W_att   [8192,64] x [64,64]   (unchanged)
// ---------------------------------------------------------------------------
__global__ __launch_bounds__(256) void k_hatt(const float* __restrict__ h,
                                              const float* __restrict__ W) {
    int row = blockIdx.x * 4 + threadIdx.y;
    int f = threadIdx.x;
    const float4* hr = (const float4*)(h + (size_t)row * Fin);

    float a0 = 0.f, a1 = 0.f, a2 = 0.f, a3 = 0.f;
#pragma unroll
    for (int k = 0; k < 16; k++) {
        float4 hv = __ldg(hr + k);
        a0 += hv.x * __ldg(W + (4 * k + 0) * 64 + f);
        a1 += hv.y * __ldg(W + (4 * k + 1) * 64 + f);
        a2 += hv.z * __ldg(W + (4 * k + 2) * 64 + f);
        a3 += hv.w * __ldg(W + (4 * k + 3) * 64 + f);
    }
    g_hatt[(size_t)row * Fin + f] = (a0 + a1) + (a2 + a3);
}

// ---------------------------------------------------------------------------
// Ballot compaction helpers
// ---------------------------------------------------------------------------
__device__ __forceinline__ void compactN(float4 v, int jbase, int lane,
                                         int& count, int* list) {
    unsigned lt = (1u << lane) - 1u;
#pragma unroll
    for (int c = 0; c < 4; c++) {
        float vv = (c == 0) ? v.x : (c == 1) ? v.y : (c == 2) ? v.z : v.w;
        bool nzme = (vv != 0.f);
        unsigned nz = __ballot_sync(0xffffffffu, nzme);
        if (nzme) {
            int slot = count + __popc(nz & lt);
            if (slot < CAP) {
                int j = jbase + lane * 4 + c;
                list[slot] = (vv > 0.f) ? j : ~j;
            }
        }
        count += __popc(nz);
    }
}

__device__ __forceinline__ void compactE(float4 v, int jbase, int lane,
                                         int& count, unsigned long long* lrow) {
    unsigned lt = (1u << lane) - 1u;
#pragma unroll
    for (int c = 0; c < 4; c++) {
        float vv = (c == 0) ? v.x : (c == 1) ? v.y : (c == 2) ? v.z : v.w;
        bool nzme = (vv != 0.f);
        unsigned nz = __ballot_sync(0xffffffffu, nzme);
        if (nzme) {
            int slot = count + __popc(nz & lt);
            if (slot < CAP) {
                unsigned long long pk =
                    ((unsigned long long)__float_as_uint(vv) << 32) |
                    (unsigned)(jbase + lane * 4 + c);
                lrow[slot] = pk;  // 21MB total, stays L2-resident for k_soft
            }
        }
        count += __popc(nz);
    }
}

// ---------------------------------------------------------------------------
// Kernel 2 (k_scan): warp-specialized scan (R6 structure), MLP=4.
// 2048 blocks x 8 warps, 4 rows per block:
//   warps 0-3: node_adj scan for row base+w   -> smem list -> g_hatt -> e
//   warps 4-7: edge_adj scan for row base+w-4 -> packed global list + count
//              + attention-row zero-fill interleaved (3rd DRAM stream)
// 4 x 512B loads in flight per warp before the ballot chains consume them.
// ---------------------------------------------------------------------------
__global__ __launch_bounds__(256) void k_scan(const float* __restrict__ node_adj,
                                              const float* __restrict__ edge_adj,
                                              const float* __restrict__ a,
                                              float* __restrict__ out_attn) {
    __shared__ int snj[4][CAP];

    int w = threadIdx.x >> 5;
    int lane = threadIdx.x & 31;

    if (w < 4) {
        // ---------------- node warps: e[row] ----------------
        int row = blockIdx.x * 4 + w;
        const float4* na4 = (const float4*)(node_adj + (size_t)row * Nn);
        int cn = 0;
#pragma unroll 1
        for (int it = 0; it < Nn / 128; it += 4) {
            float4 v0 = na4[(it + 0) * 32 + lane];
            float4 v1 = na4[(it + 1) * 32 + lane];
            float4 v2 = na4[(it + 2) * 32 + lane];
            float4 v3 = na4[(it + 3) * 32 + lane];
            compactN(v0, (it + 0) * 128, lane, cn, snj[w]);
            compactN(v1, (it + 1) * 128, lane, cn, snj[w]);
            compactN(v2, (it + 2) * 128, lane, cn, snj[w]);
            compactN(v3, (it + 3) * 128, lane, cn, snj[w]);
        }
        if (cn > CAP) cn = CAP;
        __syncwarp();

        float2 acc = make_float2(0.f, 0.f);
#pragma unroll 4
        for (int k = 0; k < cn; k++) {
            int s = snj[w][k];
            float sign = 1.f;
            int j = s;
            if (s < 0) { j = ~s; sign = -1.f; }
            float2 hv = ((const float2*)(g_hatt + (size_t)j * Fin))[lane];
            acc.x += sign * hv.x;
            acc.y += sign * hv.y;
        }
        float pa = fabsf(acc.x) * __ldg(a + 2 * lane) + fabsf(acc.y) * __ldg(a + 2 * lane + 1);
#pragma unroll
        for (int o = 16; o; o >>= 1) pa += __shfl_xor_sync(0xffffffffu, pa, o);
        if (lane == 0) g_e[row] = (pa > 0.f) ? pa : 0.2f * pa;
    } else {
        // -------- edge warps: packed list + zero-fill (3 streams live) -----
        int row = blockIdx.x * 4 + (w - 4);
        const float4* ea4 = (const float4*)(edge_adj + (size_t)row * Nn);
        float4* arow4 = out_attn ? (float4*)(out_attn + (size_t)row * Nn) : nullptr;
        unsigned long long* lrow = g_list + (size_t)row * CAP;
        float4 z4 = make_float4(0.f, 0.f, 0.f, 0.f);
        int ce = 0;
#pragma unroll 1
        for (int it = 0; it < Nn / 128; it += 4) {
            float4 v0 = ea4[(it + 0) * 32 + lane];
            float4 v1 = ea4[(it + 1) * 32 + lane];
            float4 v2 = ea4[(it + 2) * 32 + lane];
            float4 v3 = ea4[(it + 3) * 32 + lane];
            if (arow4) {                       // fire-and-forget fill overlaps loads
                arow4[(it + 0) * 32 + lane] = z4;
                arow4[(it + 1) * 32 + lane] = z4;
                arow4[(it + 2) * 32 + lane] = z4;
                arow4[(it + 3) * 32 + lane] = z4;
            }
            compactE(v0, (it + 0) * 128, lane, ce, lrow);
            compactE(v1, (it + 1) * 128, lane, ce, lrow);
            compactE(v2, (it + 2) * 128, lane, ce, lrow);
            compactE(v3, (it + 3) * 128, lane, ce, lrow);
        }
        if (lane == 0) g_cnt[row] = (ce < CAP) ? ce : CAP;
    }
}

// ---------------------------------------------------------------------------
// Kernel 3 (k_soft): pure L2/LTS work (warp per row), identical to R6:
//   read packed list (L2 hit), gather e, softmax, gather h, scatter probs,
//   write h_prime. Empty row: uniform 1/N attention, zero h_prime.
// ---------------------------------------------------------------------------
__global__ __launch_bounds__(256) void k_soft(const float* __restrict__ h,
                                              float* __restrict__ out_hp,
                                              float* __restrict__ out_attn) {
    __shared__ int   sj[8][CAP];
    __shared__ float sv[8][CAP];
    __shared__ float sp[8][CAP];

    int w = threadIdx.x >> 5;
    int lane = threadIdx.x & 31;
    int row = blockIdx.x * 8 + w;

    int count = g_cnt[row];
    float* arow = out_attn ? out_attn + (size_t)row * Nn : nullptr;

    if (count == 0) {
        if (arow) {
            float u = 1.f / (float)Nn;
            float4 u4 = make_float4(u, u, u, u);
            for (int it = 0; it < Nn / 128; ++it)
                ((float4*)arow)[it * 32 + lane] = u4;
        }
        if (out_hp)
            ((float2*)(out_hp + (size_t)row * Fin))[lane] = make_float2(0.f, 0.f);
        return;
    }

    const unsigned long long* lrow = g_list + (size_t)row * CAP;

    // unpack list + gather e + row max
    float m = -3.4e38f;
    for (int k = lane; k < count; k += 32) {
        unsigned long long pk = lrow[k];
        int j = (int)(unsigned)pk;
        sj[w][k] = j;
        sv[w][k] = __uint_as_float((unsigned)(pk >> 32));
        float e = g_e[j];
        sp[w][k] = e;
        m = fmaxf(m, e);
    }
#pragma unroll
    for (int o = 16; o; o >>= 1) m = fmaxf(m, __shfl_xor_sync(0xffffffffu, m, o));
    __syncwarp();

    // probs + denom (tol is 1e-3 -> __expf fine)
    float dsum = 0.f;
    for (int k = lane; k < count; k += 32) {
        float p = __expf(sp[w][k] - m);
        sp[w][k] = p;
        dsum += p;
    }
#pragma unroll
    for (int o = 16; o; o >>= 1) dsum += __shfl_xor_sync(0xffffffffu, dsum, o);
    float inv = 1.f / dsum;
    __syncwarp();

    // h_prime accumulation (h is 2MB, L2-resident)
    if (out_hp) {
        float2 acc = make_float2(0.f, 0.f);
#pragma unroll 4
        for (int k = 0; k < count; k++) {
            float wgt = sp[w][k] * inv * sv[w][k];
            float2 hv = ((const float2*)(h + (size_t)sj[w][k] * Fin))[lane];
            acc.x += wgt * hv.x;
            acc.y += wgt * hv.y;
        }
        ((float2*)(out_hp + (size_t)row * Fin))[lane] = acc;
    }

    // scatter softmax probs over the zero fill done by k_scan
    if (arow) {
        for (int k = lane; k < count; k += 32)
            arow[sj[w][k]] = sp[w][k] * inv;
    }
}

// ---------------------------------------------------------------------------
extern "C" void kernel_launch(void* const* d_in, const int* in_sizes, int n_in,
                              void* d_out, int out_size) {
    const float* h        = (const float*)d_in[0];
    const float* node_adj = (const float*)d_in[1];
    const float* edge_adj = (const float*)d_in[2];
    const float* W_att    = (const float*)d_in[3];
    const float* a        = (const float*)d_in[4];

    float* out = (float*)d_out;
    float* out_hp = nullptr;
    float* out_attn = nullptr;
    long long full = (long long)Nn * Fin + (long long)Nn * Nn;
    if ((long long)out_size >= full) {
        out_hp = out;
        out_attn = out + (size_t)Nn * Fin;
    } else if (out_size == Nn * Fin) {
        out_hp = out;
    } else {
        out_attn = out;  // attention only
    }

    dim3 b1(64, 4);
    k_hatt<<<Nn / 4, b1>>>(h, W_att);
    k_scan<<<Nn / 4, 256>>>(node_adj, edge_adj, a, out_attn);
    k_soft<<<Nn / 8, 256>>>(h, out_hp, out_attn);
}

// round 10
// speedup vs baseline: 1.1995x; 1.1995x over previous
#include <cuda_runtime.h>
#include <math.h>

#define Nn 8192
#define Fin 64
#define CAP 320     // max nonzeros/row: Binomial(8192,0.02): mean 164, sd 12.7 -> +12 sigma

// Scratch (device globals, no allocation)
__device__ float g_hatt[Nn * Fin];                       // h @ W_att
__device__ float g_e[Nn];                                // leaky_relu(|h+ - h-| @ a)
__device__ unsigned long long g_list[(size_t)Nn * CAP];  // packed (val<<32 | j) per edge nonzero
__device__ int g_cnt[Nn];                                // edge nonzeros per row

// ---------------------------------------------------------------------------
// Kernel 1: h_att = h @ W_att   [8192,64] x [64,64]
// Triggers programmatic launch completion after its stores so k_scan's node
// warps can gridsync on it while k_scan's scan phase runs underneath.
// ---------------------------------------------------------------------------
__global__ __launch_bounds__(256) void k_hatt(const float* __restrict__ h,
                                              const float* __restrict__ W) {
    int row = blockIdx.x * 4 + threadIdx.y;
    int f = threadIdx.x;
    const float4* hr = (const float4*)(h + (size_t)row * Fin);

    float a0 = 0.f, a1 = 0.f, a2 = 0.f, a3 = 0.f;
#pragma unroll
    for (int k = 0; k < 16; k++) {
        float4 hv = __ldg(hr + k);
        a0 += hv.x * __ldg(W + (4 * k + 0) * 64 + f);
        a1 += hv.y * __ldg(W + (4 * k + 1) * 64 + f);
        a2 += hv.z * __ldg(W + (4 * k + 2) * 64 + f);
        a3 += hv.w * __ldg(W + (4 * k + 3) * 64 + f);
    }
    g_hatt[(size_t)row * Fin + f] = (a0 + a1) + (a2 + a3);
    cudaTriggerProgrammaticLaunchCompletion();
}

// ---------------------------------------------------------------------------
// Ballot compaction helpers
// ---------------------------------------------------------------------------
__device__ __forceinline__ void compactN(float4 v, int jbase, int lane,
                                         int& count, int* list) {
    unsigned lt = (1u << lane) - 1u;
#pragma unroll
    for (int c = 0; c < 4; c++) {
        float vv = (c == 0) ? v.x : (c == 1) ? v.y : (c == 2) ? v.z : v.w;
        bool nzme = (vv != 0.f);
        unsigned nz = __ballot_sync(0xffffffffu, nzme);
        if (nzme) {
            int slot = count + __popc(nz & lt);
            if (slot < CAP) {
                int j = jbase + lane * 4 + c;
                list[slot] = (vv > 0.f) ? j : ~j;
            }
        }
        count += __popc(nz);
    }
}

__device__ __forceinline__ void compactE(float4 v, int jbase, int lane,
                                         int& count, unsigned long long* lrow) {
    unsigned lt = (1u << lane) - 1u;
#pragma unroll
    for (int c = 0; c < 4; c++) {
        float vv = (c == 0) ? v.x : (c == 1) ? v.y : (c == 2) ? v.z : v.w;
        bool nzme = (vv != 0.f);
        unsigned nz = __ballot_sync(0xffffffffu, nzme);
        if (nzme) {
            int slot = count + __popc(nz & lt);
            if (slot < CAP) {
                unsigned long long pk =
                    ((unsigned long long)__float_as_uint(vv) << 32) |
                    (unsigned)(jbase + lane * 4 + c);
                lrow[slot] = pk;  // 21MB total; L2-resident thanks to ldcs/stcs
            }
        }
        count += __popc(nz);
    }
}

// ---------------------------------------------------------------------------
// Kernel 2 (k_scan): warp-specialized scan (R6 structure, MLP=2).
// 2048 blocks x 8 warps, 4 rows per block:
//   warps 0-3: node_adj scan for row base+w   -> smem list -> g_hatt -> e
//              (gridsync on k_hatt only right before the gather phase)
//   warps 4-7: edge_adj scan for row base+w-4 -> packed global list + count
//              + attention-row zero-fill interleaved (3rd DRAM stream)
// Adjacency reads are evict-first (__ldcs); attention fill is evict-first
// (__stcs): neither is ever re-read, keeping g_list/g_hatt/h hot in L2.
// ---------------------------------------------------------------------------
__global__ __launch_bounds__(256) void k_scan(const float* __restrict__ node_adj,
                                              const float* __restrict__ edge_adj,
                                              const float* __restrict__ a,
                                              float* __restrict__ out_attn) {
    __shared__ int snj[4][CAP];

    int w = threadIdx.x >> 5;
    int lane = threadIdx.x & 31;

    if (w < 4) {
        // ---------------- node warps: e[row] ----------------
        int row = blockIdx.x * 4 + w;
        const float4* na4 = (const float4*)(node_adj + (size_t)row * Nn);
        int cn = 0;
#pragma unroll 1
        for (int it = 0; it < Nn / 128; it += 2) {
            float4 v0 = __ldcs(na4 + it * 32 + lane);
            float4 v1 = __ldcs(na4 + it * 32 + 32 + lane);
            compactN(v0, it * 128, lane, cn, snj[w]);
            compactN(v1, it * 128 + 128, lane, cn, snj[w]);
        }
        if (cn > CAP) cn = CAP;
        __syncwarp();

        // wait for k_hatt's g_hatt to be visible (PDL); the scan above ran
        // concurrently with k_hatt.
        cudaGridDependencySynchronize();

        float2 acc = make_float2(0.f, 0.f);
#pragma unroll 4
        for (int k = 0; k < cn; k++) {
            int s = snj[w][k];
            float sign = 1.f;
            int j = s;
            if (s < 0) { j = ~s; sign = -1.f; }
            float2 hv = ((const float2*)(g_hatt + (size_t)j * Fin))[lane];
            acc.x += sign * hv.x;
            acc.y += sign * hv.y;
        }
        float pa = fabsf(acc.x) * __ldg(a + 2 * lane) + fabsf(acc.y) * __ldg(a + 2 * lane + 1);
#pragma unroll
        for (int o = 16; o; o >>= 1) pa += __shfl_xor_sync(0xffffffffu, pa, o);
        if (lane == 0) g_e[row] = (pa > 0.f) ? pa : 0.2f * pa;
    } else {
        // -------- edge warps: packed list + zero-fill (3 streams live) -----
        int row = blockIdx.x * 4 + (w - 4);
        const float4* ea4 = (const float4*)(edge_adj + (size_t)row * Nn);
        float4* arow4 = out_attn ? (float4*)(out_attn + (size_t)row * Nn) : nullptr;
        unsigned long long* lrow = g_list + (size_t)row * CAP;
        float4 z4 = make_float4(0.f, 0.f, 0.f, 0.f);
        int ce = 0;
#pragma unroll 1
        for (int it = 0; it < Nn / 128; it += 2) {
            float4 v0 = __ldcs(ea4 + it * 32 + lane);
            float4 v1 = __ldcs(ea4 + it * 32 + 32 + lane);
            if (arow4) {                       // fire-and-forget fill overlaps loads
                __stcs(arow4 + it * 32 + lane, z4);
                __stcs(arow4 + it * 32 + 32 + lane, z4);
            }
            compactE(v0, it * 128, lane, ce, lrow);
            compactE(v1, it * 128 + 128, lane, ce, lrow);
        }
        if (lane == 0) g_cnt[row] = (ce < CAP) ? ce : CAP;
    }
}

// ---------------------------------------------------------------------------
// Kernel 3 (k_soft): pure L2/LTS work (warp per row), R6 body:
//   read packed list (L2-hot), gather e, softmax, gather h, scatter probs
//   (evict-first: never re-read), write h_prime.
// Empty row: uniform 1/N attention, zero h_prime.
// ---------------------------------------------------------------------------
__global__ __launch_bounds__(256) void k_soft(const float* __restrict__ h,
                                              float* __restrict__ out_hp,
                                              float* __restrict__ out_attn) {
    __shared__ int   sj[8][CAP];
    __shared__ float sv[8][CAP];
    __shared__ float sp[8][CAP];

    int w = threadIdx.x >> 5;
    int lane = threadIdx.x & 31;
    int row = blockIdx.x * 8 + w;

    int count = g_cnt[row];
    float* arow = out_attn ? out_attn + (size_t)row * Nn : nullptr;

    if (count == 0) {
        if (arow) {
            float u = 1.f / (float)Nn;
            float4 u4 = make_float4(u, u, u, u);
            for (int it = 0; it < Nn / 128; ++it)
                __stcs((float4*)arow + it * 32 + lane, u4);
        }
        if (out_hp)
            ((float2*)(out_hp + (size_t)row * Fin))[lane] = make_float2(0.f, 0.f);
        return;
    }

    const unsigned long long* lrow = g_list + (size_t)row * CAP;

    // unpack list + gather e + row max
    float m = -3.4e38f;
    for (int k = lane; k < count; k += 32) {
        unsigned long long pk = lrow[k];
        int j = (int)(unsigned)pk;
        sj[w][k] = j;
        sv[w][k] = __uint_as_float((unsigned)(pk >> 32));
        float e = g_e[j];
        sp[w][k] = e;
        m = fmaxf(m, e);
    }
#pragma unroll
    for (int o = 16; o; o >>= 1) m = fmaxf(m, __shfl_xor_sync(0xffffffffu, m, o));
    __syncwarp();

    // probs + denom (tol is 1e-3 -> __expf fine)
    float dsum = 0.f;
    for (int k = lane; k < count; k += 32) {
        float p = __expf(sp[w][k] - m);
        sp[w][k] = p;
        dsum += p;
    }
#pragma unroll
    for (int o = 16; o; o >>= 1) dsum += __shfl_xor_sync(0xffffffffu, dsum, o);
    float inv = 1.f / dsum;
    __syncwarp();

    // h_prime accumulation (h is 2MB, L2-resident)
    if (out_hp) {
        float2 acc = make_float2(0.f, 0.f);
#pragma unroll 4
        for (int k = 0; k < count; k++) {
            float wgt = sp[w][k] * inv * sv[w][k];
            float2 hv = ((const float2*)(h + (size_t)sj[w][k] * Fin))[lane];
            acc.x += wgt * hv.x;
            acc.y += wgt * hv.y;
        }
        ((float2*)(out_hp + (size_t)row * Fin))[lane] = acc;
    }

    // scatter softmax probs over the zero fill done by k_scan (never re-read)
    if (arow) {
        for (int k = lane; k < count; k += 32)
            __stcs(arow + sj[w][k], sp[w][k] * inv);
    }
}

// ---------------------------------------------------------------------------
extern "C" void kernel_launch(void* const* d_in, const int* in_sizes, int n_in,
                              void* d_out, int out_size) {
    const float* h        = (const float*)d_in[0];
    const float* node_adj = (const float*)d_in[1];
    const float* edge_adj = (const float*)d_in[2];
    const float* W_att    = (const float*)d_in[3];
    const float* a        = (const float*)d_in[4];

    float* out = (float*)d_out;
    float* out_hp = nullptr;
    float* out_attn = nullptr;
    long long full = (long long)Nn * Fin + (long long)Nn * Nn;
    if ((long long)out_size >= full) {
        out_hp = out;
        out_attn = out + (size_t)Nn * Fin;
    } else if (out_size == Nn * Fin) {
        out_hp = out;
    } else {
        out_attn = out;  // attention only
    }

    dim3 b1(64, 4);
    k_hatt<<<Nn / 4, b1>>>(h, W_att);

    // k_scan with programmatic stream serialization: it launches while k_hatt
    // drains; node warps gridsync before touching g_hatt.
    cudaLaunchConfig_t cfg = {};
    cfg.gridDim = dim3(Nn / 4);
    cfg.blockDim = dim3(256);
    cfg.dynamicSmemBytes = 0;
    cfg.stream = 0;  // legacy default stream (same as <<<>>>), graph-captured
    cudaLaunchAttribute attrs[1];
    attrs[0].id = cudaLaunchAttributeProgrammaticStreamSerialization;
    attrs[0].val.programmaticStreamSerializationAllowed = 1;
    cfg.attrs = attrs;
    cfg.numAttrs = 1;
    cudaLaunchKernelEx(&cfg, k_scan, node_adj, edge_adj, a, out_attn);

    k_soft<<<Nn / 8, 256>>>(h, out_hp, out_attn);
}

// round 11
// speedup vs baseline: 1.2348x; 1.0294x over previous
#include <cuda_runtime.h>
#include <math.h>

#define Nn 8192
#define Fin 64
#define CAP 320     // max nonzeros/row: Binomial(8192,0.02): mean 164, sd 12.7 -> +12 sigma

// Scratch (device globals, no allocation)
__device__ float g_hatt[Nn * Fin];                       // h @ W_att
__device__ float g_e[Nn];                                // leaky_relu(|h+ - h-| @ a)
__device__ unsigned long long g_list[(size_t)Nn * CAP];  // packed (val<<32 | j) per edge nonzero
__device__ int g_cnt[Nn];                                // edge nonzeros per row

// ---------------------------------------------------------------------------
// Kernel 1: h_att = h @ W_att   [8192,64] x [64,64]   (R6 version, unchanged)
// ---------------------------------------------------------------------------
__global__ __launch_bounds__(256) void k_hatt(const float* __restrict__ h,
                                              const float* __restrict__ W) {
    int row = blockIdx.x * 4 + threadIdx.y;
    int f = threadIdx.x;
    const float4* hr = (const float4*)(h + (size_t)row * Fin);

    float a0 = 0.f, a1 = 0.f, a2 = 0.f, a3 = 0.f;
#pragma unroll
    for (int k = 0; k < 16; k++) {
        float4 hv = __ldg(hr + k);
        a0 += hv.x * __ldg(W + (4 * k + 0) * 64 + f);
        a1 += hv.y * __ldg(W + (4 * k + 1) * 64 + f);
        a2 += hv.z * __ldg(W + (4 * k + 2) * 64 + f);
        a3 += hv.w * __ldg(W + (4 * k + 3) * 64 + f);
    }
    g_hatt[(size_t)row * Fin + f] = (a0 + a1) + (a2 + a3);
}

// ---------------------------------------------------------------------------
// Ballot compaction helpers (unchanged)
// ---------------------------------------------------------------------------
__device__ __forceinline__ void compactN(float4 v, int jbase, int lane,
                                         int& count, int* list) {
    unsigned lt = (1u << lane) - 1u;
#pragma unroll
    for (int c = 0; c < 4; c++) {
        float vv = (c == 0) ? v.x : (c == 1) ? v.y : (c == 2) ? v.z : v.w;
        bool nzme = (vv != 0.f);
        unsigned nz = __ballot_sync(0xffffffffu, nzme);
        if (nzme) {
            int slot = count + __popc(nz & lt);
            if (slot < CAP) {
                int j = jbase + lane * 4 + c;
                list[slot] = (vv > 0.f) ? j : ~j;
            }
        }
        count += __popc(nz);
    }
}

__device__ __forceinline__ void compactE(float4 v, int jbase, int lane,
                                         int& count, unsigned long long* lrow) {
    unsigned lt = (1u << lane) - 1u;
#pragma unroll
    for (int c = 0; c < 4; c++) {
        float vv = (c == 0) ? v.x : (c == 1) ? v.y : (c == 2) ? v.z : v.w;
        bool nzme = (vv != 0.f);
        unsigned nz = __ballot_sync(0xffffffffu, nzme);
        if (nzme) {
            int slot = count + __popc(nz & lt);
            if (slot < CAP) {
                unsigned long long pk =
                    ((unsigned long long)__float_as_uint(vv) << 32) |
                    (unsigned)(jbase + lane * 4 + c);
                lrow[slot] = pk;  // 21MB total, mostly L2-resident for k_soft
            }
        }
        count += __popc(nz);
    }
}

// ---------------------------------------------------------------------------
// Kernel 2 (k_scan): warp-specialized PURE-READ scan (R6 minus zero-fill).
// 2048 blocks x 8 warps, 4 rows per block, MLP=2:
//   warps 0-3: node_adj scan for row base+w   -> smem list -> g_hatt -> e
//   warps 4-7: edge_adj scan for row base+w-4 -> packed global list + count
// Two read streams overlap chip-wide; no write stream (k_soft owns it now).
// ---------------------------------------------------------------------------
__global__ __launch_bounds__(256) void k_scan(const float* __restrict__ node_adj,
                                              const float* __restrict__ edge_adj,
                                              const float* __restrict__ a) {
    __shared__ int snj[4][CAP];

    int w = threadIdx.x >> 5;
    int lane = threadIdx.x & 31;

    if (w < 4) {
        int row = blockIdx.x * 4 + w;
        const float4* na4 = (const float4*)(node_adj + (size_t)row * Nn);
        int cn = 0;
#pragma unroll 1
        for (int it = 0; it < Nn / 128; it += 2) {
            float4 v0 = na4[it * 32 + lane];
            float4 v1 = na4[it * 32 + 32 + lane];
            compactN(v0, it * 128, lane, cn, snj[w]);
            compactN(v1, it * 128 + 128, lane, cn, snj[w]);
        }
        if (cn > CAP) cn = CAP;
        __syncwarp();

        float2 acc = make_float2(0.f, 0.f);
#pragma unroll 4
        for (int k = 0; k < cn; k++) {
            int s = snj[w][k];
            float sign = 1.f;
            int j = s;
            if (s < 0) { j = ~s; sign = -1.f; }
            float2 hv = ((const float2*)(g_hatt + (size_t)j * Fin))[lane];
            acc.x += sign * hv.x;
            acc.y += sign * hv.y;
        }
        float pa = fabsf(acc.x) * __ldg(a + 2 * lane) + fabsf(acc.y) * __ldg(a + 2 * lane + 1);
#pragma unroll
        for (int o = 16; o; o >>= 1) pa += __shfl_xor_sync(0xffffffffu, pa, o);
        if (lane == 0) g_e[row] = (pa > 0.f) ? pa : 0.2f * pa;
    } else {
        int row = blockIdx.x * 4 + (w - 4);
        const float4* ea4 = (const float4*)(edge_adj + (size_t)row * Nn);
        unsigned long long* lrow = g_list + (size_t)row * CAP;
        int ce = 0;
#pragma unroll 1
        for (int it = 0; it < Nn / 128; it += 2) {
            float4 v0 = ea4[it * 32 + lane];
            float4 v1 = ea4[it * 32 + 32 + lane];
            compactE(v0, it * 128, lane, ce, lrow);
            compactE(v1, it * 128 + 128, lane, ce, lrow);
        }
        if (lane == 0) g_cnt[row] = (ce < CAP) ? ce : CAP;
    }
}

// ---------------------------------------------------------------------------
// Kernel 3 (k_soft): ONE ROW PER BLOCK (8192 blocks x 256 threads).
// Compose the attention row in a 32KB smem buffer and write it ONCE with
// full-sector coalesced stores (no zero-fill kernel pass, no scattered 4B
// DRAM stores, no ECC read-modify-write).
//   1. zero smem row
//   2. block-wide softmax over the packed list (count <= 320 < 512 = 2/thread)
//   3. scatter probs into smem
//   4. block-cooperative h_prime (8 warps split the nonzeros)
//   5. stream the 32KB row to gmem
// Empty row: uniform 1/N attention, zero h_prime.
// ---------------------------------------------------------------------------
__global__ __launch_bounds__(256) void k_soft(const float* __restrict__ h,
                                              float* __restrict__ out_hp,
                                              float* __restrict__ out_attn) {
    __shared__ float srow[Nn];        // 32 KB dense attention row
    __shared__ int   sj[CAP];
    __shared__ float sw[CAP];         // prob*inv*edge_val (h_prime weights)
    __shared__ float sred[8 * 64];    // per-warp h_prime partials
    __shared__ float rmax[8], rsum[8];

    int tid = threadIdx.x;
    int w = tid >> 5;
    int lane = tid & 31;
    int row = blockIdx.x;

    int count = g_cnt[row];           // uniform within the block
    float* arow = out_attn ? out_attn + (size_t)row * Nn : nullptr;

    if (count == 0) {
        if (arow) {
            float u = 1.f / (float)Nn;
            float4 u4 = make_float4(u, u, u, u);
            for (int i = tid; i < Nn / 4; i += 256) ((float4*)arow)[i] = u4;
        }
        if (out_hp && tid < 32)
            ((float2*)(out_hp + (size_t)row * Fin))[tid] = make_float2(0.f, 0.f);
        return;
    }

    // 1. zero the smem row (stores only; completion covered by the sync below)
    float4 z4 = make_float4(0.f, 0.f, 0.f, 0.f);
    for (int i = tid; i < Nn / 4; i += 256) ((float4*)srow)[i] = z4;

    // 2. load list: thread handles k = tid and k = tid + 256
    const unsigned long long* lrow = g_list + (size_t)row * CAP;
    int   j0 = 0, j1 = 0;
    float v0 = 0.f, v1 = 0.f, e0 = -3.4e38f, e1 = -3.4e38f;
    if (tid < count) {
        unsigned long long pk = lrow[tid];
        j0 = (int)(unsigned)pk;
        v0 = __uint_as_float((unsigned)(pk >> 32));
        e0 = g_e[j0];
    }
    if (tid + 256 < count) {
        unsigned long long pk = lrow[tid + 256];
        j1 = (int)(unsigned)pk;
        v1 = __uint_as_float((unsigned)(pk >> 32));
        e1 = g_e[j1];
    }

    // block max
    float m = fmaxf(e0, e1);
#pragma unroll
    for (int o = 16; o; o >>= 1) m = fmaxf(m, __shfl_xor_sync(0xffffffffu, m, o));
    if (lane == 0) rmax[w] = m;
    __syncthreads();
    m = rmax[0];
#pragma unroll
    for (int q = 1; q < 8; q++) m = fmaxf(m, rmax[q]);

    // block sum of exp
    float p0 = (tid < count) ? __expf(e0 - m) : 0.f;
    float p1 = (tid + 256 < count) ? __expf(e1 - m) : 0.f;
    float s = p0 + p1;
#pragma unroll
    for (int o = 16; o; o >>= 1) s += __shfl_xor_sync(0xffffffffu, s, o);
    if (lane == 0) rsum[w] = s;
    __syncthreads();
    float denom = rsum[0];
#pragma unroll
    for (int q = 1; q < 8; q++) denom += rsum[q];
    float inv = 1.f / denom;

    // 3. scatter probs into smem row + record h_prime weights
    if (tid < count) {
        float pr = p0 * inv;
        srow[j0] = pr;
        sj[tid] = j0;
        sw[tid] = pr * v0;
    }
    if (tid + 256 < count) {
        float pr = p1 * inv;
        srow[j1] = pr;
        sj[tid + 256] = j1;
        sw[tid + 256] = pr * v1;
    }
    __syncthreads();

    // 4. h_prime: warp w takes nonzeros k = w, w+8, ... (h rows L2-resident)
    float2 acc = make_float2(0.f, 0.f);
#pragma unroll 2
    for (int k = w; k < count; k += 8) {
        float wgt = sw[k];
        float2 hv = ((const float2*)(h + (size_t)sj[k] * Fin))[lane];
        acc.x += wgt * hv.x;
        acc.y += wgt * hv.y;
    }
    sred[w * 64 + 2 * lane + 0] = acc.x;
    sred[w * 64 + 2 * lane + 1] = acc.y;
    __syncthreads();
    if (out_hp && w == 0) {
        float sx = 0.f, sy = 0.f;
#pragma unroll
        for (int q = 0; q < 8; q++) {
            sx += sred[q * 64 + 2 * lane + 0];
            sy += sred[q * 64 + 2 * lane + 1];
        }
        ((float2*)(out_hp + (size_t)row * Fin))[lane] = make_float2(sx, sy);
    }

    // 5. stream the composed row out: 32KB of full-sector coalesced stores
    if (arow) {
        for (int i = tid; i < Nn / 4; i += 256)
            ((float4*)arow)[i] = ((const float4*)srow)[i];
    }
}

// ---------------------------------------------------------------------------
extern "C" void kernel_launch(void* const* d_in, const int* in_sizes, int n_in,
                              void* d_out, int out_size) {
    const float* h        = (const float*)d_in[0];
    const float* node_adj = (const float*)d_in[1];
    const float* edge_adj = (const float*)d_in[2];
    const float* W_att    = (const float*)d_in[3];
    const float* a        = (const float*)d_in[4];

    float* out = (float*)d_out;
    float* out_hp = nullptr;
    float* out_attn = nullptr;
    long long full = (long long)Nn * Fin + (long long)Nn * Nn;
    if ((long long)out_size >= full) {
        out_hp = out;
        out_attn = out + (size_t)Nn * Fin;
    } else if (out_size == Nn * Fin) {
        out_hp = out;
    } else {
        out_attn = out;  // attention only
    }

    dim3 b1(64, 4);
    k_hatt<<<Nn / 4, b1>>>(h, W_att);
    k_scan<<<Nn / 4, 256>>>(node_adj, edge_adj, a);
    k_soft<<<Nn, 256>>>(h, out_hp, out_attn);
}

// round 12
// speedup vs baseline: 1.2692x; 1.0279x over previous
#include <cuda_runtime.h>
#include <math.h>

#define Nn 8192
#define Fin 64
#define CAP 320     // max nonzeros/row: Binomial(8192,0.02): mean 164, sd 12.7 -> +12 sigma

// Scratch (device globals, no allocation)
__device__ float g_e[Nn];                                // leaky_relu(|((A+-A-)h)W| @ a)
__device__ unsigned long long g_list[(size_t)Nn * CAP];  // packed (val<<32 | j) per edge nonzero
__device__ int g_cnt[Nn];                                // edge nonzeros per row

// ---------------------------------------------------------------------------
// Ballot compaction helpers (unchanged)
// ---------------------------------------------------------------------------
__device__ __forceinline__ void compactN(float4 v, int jbase, int lane,
                                         int& count, int* list) {
    unsigned lt = (1u << lane) - 1u;
#pragma unroll
    for (int c = 0; c < 4; c++) {
        float vv = (c == 0) ? v.x : (c == 1) ? v.y : (c == 2) ? v.z : v.w;
        bool nzme = (vv != 0.f);
        unsigned nz = __ballot_sync(0xffffffffu, nzme);
        if (nzme) {
            int slot = count + __popc(nz & lt);
            if (slot < CAP) {
                int j = jbase + lane * 4 + c;
                list[slot] = (vv > 0.f) ? j : ~j;
            }
        }
        count += __popc(nz);
    }
}

__device__ __forceinline__ void compactE(float4 v, int jbase, int lane,
                                         int& count, unsigned long long* lrow) {
    unsigned lt = (1u << lane) - 1u;
#pragma unroll
    for (int c = 0; c < 4; c++) {
        float vv = (c == 0) ? v.x : (c == 1) ? v.y : (c == 2) ? v.z : v.w;
        bool nzme = (vv != 0.f);
        unsigned nz = __ballot_sync(0xffffffffu, nzme);
        if (nzme) {
            int slot = count + __popc(nz & lt);
            if (slot < CAP) {
                unsigned long long pk =
                    ((unsigned long long)__float_as_uint(vv) << 32) |
                    (unsigned)(jbase + lane * 4 + c);
                lrow[slot] = pk;  // 21MB total, mostly L2-resident for k_soft
            }
        }
        count += __popc(nz);
    }
}

// ---------------------------------------------------------------------------
// Kernel 1 (k_scan): warp-specialized PURE-READ scan.
// 2048 blocks x 8 warps, 4 rows per block, MLP=2:
//   warps 0-3: node_adj scan for row base+w -> smem list -> gather h rows ->
//              diff = sum sign*h[j]  ->  e = leaky_relu(|diff @ W| . a)
//              (matmul/aggregation linearity: (S@(h@W)) == ((S@h)@W), so the
//               k_hatt pre-pass kernel is eliminated entirely)
//   warps 4-7: edge_adj scan for row base+w-4 -> packed global list + count
// ---------------------------------------------------------------------------
__global__ __launch_bounds__(256) void k_scan(const float* __restrict__ node_adj,
                                              const float* __restrict__ edge_adj,
                                              const float* __restrict__ h,
                                              const float* __restrict__ W,
                                              const float* __restrict__ a) {
    __shared__ int   snj[4][CAP];
    __shared__ float sdiff[4][64];

    int w = threadIdx.x >> 5;
    int lane = threadIdx.x & 31;

    if (w < 4) {
        // ---------------- node warps: e[row] ----------------
        int row = blockIdx.x * 4 + w;
        const float4* na4 = (const float4*)(node_adj + (size_t)row * Nn);
        int cn = 0;
#pragma unroll 1
        for (int it = 0; it < Nn / 128; it += 2) {
            float4 v0 = na4[it * 32 + lane];
            float4 v1 = na4[it * 32 + 32 + lane];
            compactN(v0, it * 128, lane, cn, snj[w]);
            compactN(v1, it * 128 + 128, lane, cn, snj[w]);
        }
        if (cn > CAP) cn = CAP;
        __syncwarp();

        // diff = sum_j sign * h[j,:]   (h rows are 256B, L2-resident)
        float2 acc = make_float2(0.f, 0.f);
#pragma unroll 4
        for (int k = 0; k < cn; k++) {
            int s = snj[w][k];
            float sign = 1.f;
            int j = s;
            if (s < 0) { j = ~s; sign = -1.f; }
            float2 hv = ((const float2*)(h + (size_t)j * Fin))[lane];
            acc.x += sign * hv.x;
            acc.y += sign * hv.y;
        }
        sdiff[w][2 * lane + 0] = acc.x;
        sdiff[w][2 * lane + 1] = acc.y;
        __syncwarp();

        // t[f] = sum_k diff[k] * W[k,f] for f = 2*lane, 2*lane+1
        float t0 = 0.f, t1 = 0.f;
        int f0 = 2 * lane;
#pragma unroll 8
        for (int k = 0; k < 64; k++) {
            float d = sdiff[w][k];
            t0 += d * __ldg(W + k * 64 + f0);
            t1 += d * __ldg(W + k * 64 + f0 + 1);
        }
        float pa = fabsf(t0) * __ldg(a + f0) + fabsf(t1) * __ldg(a + f0 + 1);
#pragma unroll
        for (int o = 16; o; o >>= 1) pa += __shfl_xor_sync(0xffffffffu, pa, o);
        if (lane == 0) g_e[row] = (pa > 0.f) ? pa : 0.2f * pa;
    } else {
        // ---------------- edge warps: packed list + count ----------------
        int row = blockIdx.x * 4 + (w - 4);
        const float4* ea4 = (const float4*)(edge_adj + (size_t)row * Nn);
        unsigned long long* lrow = g_list + (size_t)row * CAP;
        int ce = 0;
#pragma unroll 1
        for (int it = 0; it < Nn / 128; it += 2) {
            float4 v0 = ea4[it * 32 + lane];
            float4 v1 = ea4[it * 32 + 32 + lane];
            compactE(v0, it * 128, lane, ce, lrow);
            compactE(v1, it * 128 + 128, lane, ce, lrow);
        }
        if (lane == 0) g_cnt[row] = (ce < CAP) ? ce : CAP;
    }
}

// ---------------------------------------------------------------------------
// Kernel 2 (k_soft): ONE ROW PER BLOCK (8192 blocks x 256 threads).
// Compose the attention row in a 32KB smem buffer, write once, coalesced.
// (unchanged from R11)
// ---------------------------------------------------------------------------
__global__ __launch_bounds__(256) void k_soft(const float* __restrict__ h,
                                              float* __restrict__ out_hp,
                                              float* __restrict__ out_attn) {
    __shared__ float srow[Nn];        // 32 KB dense attention row
    __shared__ int   sj[CAP];
    __shared__ float sw[CAP];         // prob*inv*edge_val (h_prime weights)
    __shared__ float sred[8 * 64];    // per-warp h_prime partials
    __shared__ float rmax[8], rsum[8];

    int tid = threadIdx.x;
    int w = tid >> 5;
    int lane = tid & 31;
    int row = blockIdx.x;

    int count = g_cnt[row];           // uniform within the block
    float* arow = out_attn ? out_attn + (size_t)row * Nn : nullptr;

    if (count == 0) {
        if (arow) {
            float u = 1.f / (float)Nn;
            float4 u4 = make_float4(u, u, u, u);
            for (int i = tid; i < Nn / 4; i += 256) ((float4*)arow)[i] = u4;
        }
        if (out_hp && tid < 32)
            ((float2*)(out_hp + (size_t)row * Fin))[tid] = make_float2(0.f, 0.f);
        return;
    }

    // 1. zero the smem row
    float4 z4 = make_float4(0.f, 0.f, 0.f, 0.f);
    for (int i = tid; i < Nn / 4; i += 256) ((float4*)srow)[i] = z4;

    // 2. load list: thread handles k = tid and k = tid + 256
    const unsigned long long* lrow = g_list + (size_t)row * CAP;
    int   j0 = 0, j1 = 0;
    float v0 = 0.f, v1 = 0.f, e0 = -3.4e38f, e1 = -3.4e38f;
    if (tid < count) {
        unsigned long long pk = lrow[tid];
        j0 = (int)(unsigned)pk;
        v0 = __uint_as_float((unsigned)(pk >> 32));
        e0 = g_e[j0];
    }
    if (tid + 256 < count) {
        unsigned long long pk = lrow[tid + 256];
        j1 = (int)(unsigned)pk;
        v1 = __uint_as_float((unsigned)(pk >> 32));
        e1 = g_e[j1];
    }

    // block max
    float m = fmaxf(e0, e1);
#pragma unroll
    for (int o = 16; o; o >>= 1) m = fmaxf(m, __shfl_xor_sync(0xffffffffu, m, o));
    if (lane == 0) rmax[w] = m;
    __syncthreads();
    m = rmax[0];
#pragma unroll
    for (int q = 1; q < 8; q++) m = fmaxf(m, rmax[q]);

    // block sum of exp
    float p0 = (tid < count) ? __expf(e0 - m) : 0.f;
    float p1 = (tid + 256 < count) ? __expf(e1 - m) : 0.f;
    float s = p0 + p1;
#pragma unroll
    for (int o = 16; o; o >>= 1) s += __shfl_xor_sync(0xffffffffu, s, o);
    if (lane == 0) rsum[w] = s;
    __syncthreads();
    float denom = rsum[0];
#pragma unroll
    for (int q = 1; q < 8; q++) denom += rsum[q];
    float inv = 1.f / denom;

    // 3. scatter probs into smem row + record h_prime weights
    if (tid < count) {
        float pr = p0 * inv;
        srow[j0] = pr;
        sj[tid] = j0;
        sw[tid] = pr * v0;
    }
    if (tid + 256 < count) {
        float pr = p1 * inv;
        srow[j1] = pr;
        sj[tid + 256] = j1;
        sw[tid + 256] = pr * v1;
    }
    __syncthreads();

    // 4. h_prime: warp w takes nonzeros k = w, w+8, ... (h rows L2-resident)
    float2 acc = make_float2(0.f, 0.f);
#pragma unroll 2
    for (int k = w; k < count; k += 8) {
        float wgt = sw[k];
        float2 hv = ((const float2*)(h + (size_t)sj[k] * Fin))[lane];
        acc.x += wgt * hv.x;
        acc.y += wgt * hv.y;
    }
    sred[w * 64 + 2 * lane + 0] = acc.x;
    sred[w * 64 + 2 * lane + 1] = acc.y;
    __syncthreads();
    if (out_hp && w == 0) {
        float sx = 0.f, sy = 0.f;
#pragma unroll
        for (int q = 0; q < 8; q++) {
            sx += sred[q * 64 + 2 * lane + 0];
            sy += sred[q * 64 + 2 * lane + 1];
        }
        ((float2*)(out_hp + (size_t)row * Fin))[lane] = make_float2(sx, sy);
    }

    // 5. stream the composed row out: 32KB of full-sector coalesced stores
    if (arow) {
        for (int i = tid; i < Nn / 4; i += 256)
            ((float4*)arow)[i] = ((const float4*)srow)[i];
    }
}

// ---------------------------------------------------------------------------
extern "C" void kernel_launch(void* const* d_in, const int* in_sizes, int n_in,
                              void* d_out, int out_size) {
    const float* h        = (const float*)d_in[0];
    const float* node_adj = (const float*)d_in[1];
    const float* edge_adj = (const float*)d_in[2];
    const float* W_att    = (const float*)d_in[3];
    const float* a        = (const float*)d_in[4];

    float* out = (float*)d_out;
    float* out_hp = nullptr;
    float* out_attn = nullptr;
    long long full = (long long)Nn * Fin + (long long)Nn * Nn;
    if ((long long)out_size >= full) {
        out_hp = out;
        out_attn = out + (size_t)Nn * Fin;
    } else if (out_size == Nn * Fin) {
        out_hp = out;
    } else {
        out_attn = out;  // attention only
    }

    k_scan<<<Nn / 4, 256>>>(node_adj, edge_adj, h, W_att, a);
    k_soft<<<Nn, 256>>>(h, out_hp, out_attn);
}

// round 14
// speedup vs baseline: 1.2943x; 1.0197x over previous
#include <cuda_runtime.h>
#include <cstdint>
#include <math.h>

#define Nn 8192
#define Fin 64
#define CAP 320     // max nonzeros/row: Binomial(8192,0.02): mean 164, sd 12.7 -> +12 sigma

// Scratch (device globals, no allocation)
__device__ float g_e[Nn];                                // leaky_relu(|((A+-A-)h)W| @ a)
__device__ unsigned long long g_list[(size_t)Nn * CAP];  // packed (val<<32 | j) per edge nonzero
__device__ int g_cnt[Nn];                                // edge nonzeros per row

// ---------------------------------------------------------------------------
// Ballot compaction helpers (unchanged)
// ---------------------------------------------------------------------------
__device__ __forceinline__ void compactN(float4 v, int jbase, int lane,
                                         int& count, int* list) {
    unsigned lt = (1u << lane) - 1u;
#pragma unroll
    for (int c = 0; c < 4; c++) {
        float vv = (c == 0) ? v.x : (c == 1) ? v.y : (c == 2) ? v.z : v.w;
        bool nzme = (vv != 0.f);
        unsigned nz = __ballot_sync(0xffffffffu, nzme);
        if (nzme) {
            int slot = count + __popc(nz & lt);
            if (slot < CAP) {
                int j = jbase + lane * 4 + c;
                list[slot] = (vv > 0.f) ? j : ~j;
            }
        }
        count += __popc(nz);
    }
}

__device__ __forceinline__ void compactE(float4 v, int jbase, int lane,
                                         int& count, unsigned long long* lrow) {
    unsigned lt = (1u << lane) - 1u;
#pragma unroll
    for (int c = 0; c < 4; c++) {
        float vv = (c == 0) ? v.x : (c == 1) ? v.y : (c == 2) ? v.z : v.w;
        bool nzme = (vv != 0.f);
        unsigned nz = __ballot_sync(0xffffffffu, nzme);
        if (nzme) {
            int slot = count + __popc(nz & lt);
            if (slot < CAP) {
                unsigned long long pk =
                    ((unsigned long long)__float_as_uint(vv) << 32) |
                    (unsigned)(jbase + lane * 4 + c);
                lrow[slot] = pk;  // 21MB total, mostly L2-resident for k_soft
            }
        }
        count += __popc(nz);
    }
}

// ---------------------------------------------------------------------------
// Kernel 1 (k_scan): warp-specialized PURE-READ scan.   (unchanged from R12)
// 2048 blocks x 8 warps, 4 rows per block, MLP=2:
//   warps 0-3: node_adj scan -> smem list -> gather h rows -> diff -> e
//              (linearity: (S@(h@W)) == ((S@h)@W); no h_att pre-pass)
//   warps 4-7: edge_adj scan -> packed global list + count
// ---------------------------------------------------------------------------
__global__ __launch_bounds__(256) void k_scan(const float* __restrict__ node_adj,
                                              const float* __restrict__ edge_adj,
                                              const float* __restrict__ h,
                                              const float* __restrict__ W,
                                              const float* __restrict__ a) {
    __shared__ int   snj[4][CAP];
    __shared__ float sdiff[4][64];

    int w = threadIdx.x >> 5;
    int lane = threadIdx.x & 31;

    if (w < 4) {
        int row = blockIdx.x * 4 + w;
        const float4* na4 = (const float4*)(node_adj + (size_t)row * Nn);
        int cn = 0;
#pragma unroll 1
        for (int it = 0; it < Nn / 128; it += 2) {
            float4 v0 = na4[it * 32 + lane];
            float4 v1 = na4[it * 32 + 32 + lane];
            compactN(v0, it * 128, lane, cn, snj[w]);
            compactN(v1, it * 128 + 128, lane, cn, snj[w]);
        }
        if (cn > CAP) cn = CAP;
        __syncwarp();

        float2 acc = make_float2(0.f, 0.f);
#pragma unroll 4
        for (int k = 0; k < cn; k++) {
            int s = snj[w][k];
            float sign = 1.f;
            int j = s;
            if (s < 0) { j = ~s; sign = -1.f; }
            float2 hv = ((const float2*)(h + (size_t)j * Fin))[lane];
            acc.x += sign * hv.x;
            acc.y += sign * hv.y;
        }
        sdiff[w][2 * lane + 0] = acc.x;
        sdiff[w][2 * lane + 1] = acc.y;
        __syncwarp();

        float t0 = 0.f, t1 = 0.f;
        int f0 = 2 * lane;
#pragma unroll 8
        for (int k = 0; k < 64; k++) {
            float d = sdiff[w][k];
            t0 += d * __ldg(W + k * 64 + f0);
            t1 += d * __ldg(W + k * 64 + f0 + 1);
        }
        float pa = fabsf(t0) * __ldg(a + f0) + fabsf(t1) * __ldg(a + f0 + 1);
#pragma unroll
        for (int o = 16; o; o >>= 1) pa += __shfl_xor_sync(0xffffffffu, pa, o);
        if (lane == 0) g_e[row] = (pa > 0.f) ? pa : 0.2f * pa;
    } else {
        int row = blockIdx.x * 4 + (w - 4);
        const float4* ea4 = (const float4*)(edge_adj + (size_t)row * Nn);
        unsigned long long* lrow = g_list + (size_t)row * CAP;
        int ce = 0;
#pragma unroll 1
        for (int it = 0; it < Nn / 128; it += 2) {
            float4 v0 = ea4[it * 32 + lane];
            float4 v1 = ea4[it * 32 + 32 + lane];
            compactE(v0, it * 128, lane, ce, lrow);
            compactE(v1, it * 128 + 128, lane, ce, lrow);
        }
        if (lane == 0) g_cnt[row] = (ce < CAP) ? ce : CAP;
    }
}

// ---------------------------------------------------------------------------
// Kernel 2 (k_soft): ONE ROW PER BLOCK (8192 blocks x 256 threads).
// Compose the attention row in smem, then push it out with ONE TMA bulk
// store (cp.async.bulk smem->gmem): no LDS read-back, no STG loop, no L1tex
// wavefronts for the copy. The TMA store overlaps the h_prime gather phase.
// ---------------------------------------------------------------------------
__global__ __launch_bounds__(256) void k_soft(const float* __restrict__ h,
                                              float* __restrict__ out_hp,
                                              float* __restrict__ out_attn) {
    __shared__ __align__(16) float srow[Nn];   // 32 KB dense attention row
    __shared__ int   sj[CAP];
    __shared__ float sw[CAP];         // prob*inv*edge_val (h_prime weights)
    __shared__ float sred[8 * 64];    // per-warp h_prime partials
    __shared__ float rmax[8], rsum[8];

    int tid = threadIdx.x;
    int w = tid >> 5;
    int lane = tid & 31;
    int row = blockIdx.x;

    int count = g_cnt[row];           // uniform within the block
    float* arow = out_attn ? out_attn + (size_t)row * Nn : nullptr;

    if (count == 0) {
        if (arow) {
            float u = 1.f / (float)Nn;
            float4 u4 = make_float4(u, u, u, u);
            for (int i = tid; i < Nn / 4; i += 256) ((float4*)arow)[i] = u4;
        }
        if (out_hp && tid < 32)
            ((float2*)(out_hp + (size_t)row * Fin))[tid] = make_float2(0.f, 0.f);
        return;
    }

    // 1. zero the smem row
    float4 z4 = make_float4(0.f, 0.f, 0.f, 0.f);
    for (int i = tid; i < Nn / 4; i += 256) ((float4*)srow)[i] = z4;

    // 2. load list: thread handles k = tid and k = tid + 256
    const unsigned long long* lrow = g_list + (size_t)row * CAP;
    int   j0 = 0, j1 = 0;
    float v0 = 0.f, v1 = 0.f, e0 = -3.4e38f, e1 = -3.4e38f;
    if (tid < count) {
        unsigned long long pk = lrow[tid];
        j0 = (int)(unsigned)pk;
        v0 = __uint_as_float((unsigned)(pk >> 32));
        e0 = g_e[j0];
    }
    if (tid + 256 < count) {
        unsigned long long pk = lrow[tid + 256];
        j1 = (int)(unsigned)pk;
        v1 = __uint_as_float((unsigned)(pk >> 32));
        e1 = g_e[j1];
    }

    // block max
    float m = fmaxf(e0, e1);
#pragma unroll
    for (int o = 16; o; o >>= 1) m = fmaxf(m, __shfl_xor_sync(0xffffffffu, m, o));
    if (lane == 0) rmax[w] = m;
    __syncthreads();
    m = rmax[0];
#pragma unroll
    for (int q = 1; q < 8; q++) m = fmaxf(m, rmax[q]);

    // block sum of exp
    float p0 = (tid < count) ? __expf(e0 - m) : 0.f;
    float p1 = (tid + 256 < count) ? __expf(e1 - m) : 0.f;
    float s = p0 + p1;
#pragma unroll
    for (int o = 16; o; o >>= 1) s += __shfl_xor_sync(0xffffffffu, s, o);
    if (lane == 0) rsum[w] = s;
    __syncthreads();
    float denom = rsum[0];
#pragma unroll
    for (int q = 1; q < 8; q++) denom += rsum[q];
    float inv = 1.f / denom;

    // 3. scatter probs into smem row + record h_prime weights
    if (tid < count) {
        float pr = p0 * inv;
        srow[j0] = pr;
        sj[tid] = j0;
        sw[tid] = pr * v0;
    }
    if (tid + 256 < count) {
        float pr = p1 * inv;
        srow[j1] = pr;
        sj[tid + 256] = j1;
        sw[tid + 256] = pr * v1;
    }
    __syncthreads();

    // 4. TMA bulk store of the composed row (issued once; overlaps step 5)
    if (arow && tid == 0) {
        asm volatile("fence.proxy.async.shared::cta;" ::: "memory");
        uint32_t saddr;
        asm("{ .reg .u64 t; cvta.to.shared.u64 t, %1; cvt.u32.u64 %0, t; }"
            : "=r"(saddr) : "l"(srow));
        asm volatile(
            "cp.async.bulk.global.shared::cta.bulk_group [%0], [%1], %2;"
            :: "l"(arow), "r"(saddr), "r"((int)(Nn * sizeof(float)))
            : "memory");
        asm volatile("cp.async.bulk.commit_group;" ::: "memory");
    }

    // 5. h_prime: warp w takes nonzeros k = w, w+8, ... (h rows L2-resident)
    float2 acc = make_float2(0.f, 0.f);
#pragma unroll 2
    for (int k = w; k < count; k += 8) {
        float wgt = sw[k];
        float2 hv = ((const float2*)(h + (size_t)sj[k] * Fin))[lane];
        acc.x += wgt * hv.x;
        acc.y += wgt * hv.y;
    }
    sred[w * 64 + 2 * lane + 0] = acc.x;
    sred[w * 64 + 2 * lane + 1] = acc.y;
    __syncthreads();
    if (out_hp && w == 0) {
        float sx = 0.f, sy = 0.f;
#pragma unroll
        for (int q = 0; q < 8; q++) {
            sx += sred[q * 64 + 2 * lane + 0];
            sy += sred[q * 64 + 2 * lane + 1];
        }
        ((float2*)(out_hp + (size_t)row * Fin))[lane] = make_float2(sx, sy);
    }

    // 6. drain the bulk store's smem reads before block exit
    if (arow && tid == 0) {
        asm volatile("cp.async.bulk.wait_group.read 0;" ::: "memory");
    }
    __syncthreads();
}

// ---------------------------------------------------------------------------
extern "C" void kernel_launch(void* const* d_in, const int* in_sizes, int n_in,
                              void* d_out, int out_size) {
    const float* h        = (const float*)d_in[0];
    const float* node_adj = (const float*)d_in[1];
    const float* edge_adj = (const float*)d_in[2];
    const float* W_att    = (const float*)d_in[3];
    const float* a        = (const float*)d_in[4];

    float* out = (float*)d_out;
    float* out_hp = nullptr;
    float* out_attn = nullptr;
    long long full = (long long)Nn * Fin + (long long)Nn * Nn;
    if ((long long)out_size >= full) {
        out_hp = out;
        out_attn = out + (size_t)Nn * Fin;
    } else if (out_size == Nn * Fin) {
        out_hp = out;
    } else {
        out_attn = out;  // attention only
    }

    k_scan<<<Nn / 4, 256>>>(node_adj, edge_adj, h, W_att, a);
    k_soft<<<Nn, 256>>>(h, out_hp, out_attn);
}